// round 12
// baseline (speedup 1.0000x reference)
#include <cuda_runtime.h>

// QuantumConv closed form (R1 derivation):
//   p1 = 0.5 - 0.5*cos(pi*t0)*cos(pi*t1)*cos(f0)
//            + 0.5*sin(pi*t0)*cos(pi*t1)*sin(f0)*cos(f1)*cos(f8)
// with f0 = in[b,y,x], f1 = in[b,y,x+1], f8 = in[b,y+2,x+2].
//
// FINAL (= R5 exact source; mode of the floor distribution at 4.608us):
//   - 9-qubit statevector collapsed analytically to a 3-pixel map (~4000x
//     fewer FLOPs): measurement projector |1><1|_0 commutes past all q1..q8
//     rotations and RZ(q0); CZ ring reduces to a cos(f1)*cos(f8) factor.
//   - MUFU __sincosf/__cosf (args within [-pi^2/2, pi^2/2]; err ~1e-6 << 1e-3).
//   - 1 output/thread, 85 x 128 1D grid, single wave — max TLP. Measured
//     strictly better than ILP-4 (+1.6us) and 416-thread blocks (+5.2us).
//   - FMA-folded epilogue with pre-halved theta constants; regs=17.
// Measured noise model: identical binary scored 4.608 / 4.608 / 5.92 / 6.37;
// internal dur stable 4.0-4.6us; all pipes <1% — harness launch floor.

#define BATCH 16
#define HH 28
#define WW 28
#define NOUT 26
#define NP (BATCH * NOUT * NOUT)   // 10816

__global__ __launch_bounds__(128, 1)
void qconv_closed_form(const float* __restrict__ in,
                       const float* __restrict__ theta,
                       float* __restrict__ out) {
    int idx = blockIdx.x * blockDim.x + threadIdx.x;
    if (idx >= NP) return;

    int t = idx / NOUT;          // const-div -> mulhi
    int x = idx - t * NOUT;
    int b = t / NOUT;
    int y = t - b * NOUT;

    const float* base = in + (b * HH + y) * WW + x;

    // Batch all 5 loads before any dependent math (MLP=5, L2-warm on replay).
    float f0 = __ldg(base);
    float f1 = __ldg(base + 1);
    float f8 = __ldg(base + 2 * WW + 2);
    float t0 = __ldg(theta);
    float t1 = __ldg(theta + 1);

    const float PI = 3.14159265358979323846f;

    // Theta MUFUs — independent of the data MUFUs below, overlap freely.
    float sa, ca;
    __sincosf(PI * t0, &sa, &ca);
    float cbh = 0.5f * __cosf(PI * t1);
    float K1h = ca * cbh;        // 0.5 * cos(pi t0) cos(pi t1)
    float K2h = sa * cbh;        // 0.5 * sin(pi t0) cos(pi t1)

    float s0, c0;
    __sincosf(f0, &s0, &c0);
    float c18 = __cosf(f1) * __cosf(f8);

    out[idx] = fmaf(K2h, s0 * c18, fmaf(-K1h, c0, 0.5f));
}

extern "C" void kernel_launch(void* const* d_in, const int* in_sizes, int n_in,
                              void* d_out, int out_size) {
    const float* input = (const float*)d_in[0];   // (16,28,28) float32
    const float* theta = (const float*)d_in[1];   // (1,27) float32
    float* out = (float*)d_out;                   // (16,26,26) float32

    (void)in_sizes; (void)n_in; (void)out_size;

    int threads = 128;
    int blocks = (NP + threads - 1) / threads;    // 85 blocks, single wave
    qconv_closed_form<<<blocks, threads>>>(input, theta, out);
}

// round 13
// speedup vs baseline: 1.4931x; 1.4931x over previous
#include <cuda_runtime.h>

// QuantumConv closed form (R1 derivation):
//   p1 = 0.5 - 0.5*cos(pi*t0)*cos(pi*t1)*cos(f0)
//            + 0.5*sin(pi*t0)*cos(pi*t1)*sin(f0)*cos(f1)*cos(f8)
// with f0 = in[b,y,x], f1 = in[b,y,x+1], f8 = in[b,y+2,x+2].
//
// R13: keep the proven 128-thread 1D block shape (max TLP; ILP-4 and fat
// blocks both measured worse) but hoist the batch index into gridDim.y:
// grid(6,16) x block(128). b = blockIdx.y is free; per-batch flat index
// (0..675) needs only ONE div-by-26 instead of two on the address critical
// path ahead of the LDGs. 96 blocks, still a single wave.
// Session noise model: identical binaries scored 4.608/4.608/5.92/6.37/6.88
// total (environment drift + replay jitter); internal dur is the stable
// metric (4.03-4.58us); all pipes <1% — launch-floor regime.

#define BATCH 16
#define HH 28
#define WW 28
#define NOUT 26
#define PERB (NOUT * NOUT)        // 676 outputs per batch image

__global__ __launch_bounds__(128, 1)
void qconv_closed_form(const float* __restrict__ in,
                       const float* __restrict__ theta,
                       float* __restrict__ out) {
    int local = blockIdx.x * 128 + threadIdx.x;   // 0..767, active if <676
    int b = blockIdx.y;                           // free from special register
    if (local >= PERB) return;

    int y = local / NOUT;        // single const-div -> mulhi+shift
    int x = local - y * NOUT;

    const float* base = in + (b * HH + y) * WW + x;

    // Batch all 5 loads before any dependent math (MLP=5, L2-warm on replay).
    float f0 = __ldg(base);
    float f1 = __ldg(base + 1);
    float f8 = __ldg(base + 2 * WW + 2);
    float t0 = __ldg(theta);
    float t1 = __ldg(theta + 1);

    const float PI = 3.14159265358979323846f;

    // Theta MUFUs — independent of the data MUFUs below, overlap freely.
    float sa, ca;
    __sincosf(PI * t0, &sa, &ca);
    float cbh = 0.5f * __cosf(PI * t1);
    float K1h = ca * cbh;        // 0.5 * cos(pi t0) cos(pi t1)
    float K2h = sa * cbh;        // 0.5 * sin(pi t0) cos(pi t1)

    float s0, c0;
    __sincosf(f0, &s0, &c0);
    float c18 = __cosf(f1) * __cosf(f8);

    out[b * PERB + local] = fmaf(K2h, s0 * c18, fmaf(-K1h, c0, 0.5f));
}

extern "C" void kernel_launch(void* const* d_in, const int* in_sizes, int n_in,
                              void* d_out, int out_size) {
    const float* input = (const float*)d_in[0];   // (16,28,28) float32
    const float* theta = (const float*)d_in[1];   // (1,27) float32
    float* out = (float*)d_out;                   // (16,26,26) float32

    (void)in_sizes; (void)n_in; (void)out_size;

    dim3 block(128);
    dim3 grid((PERB + 127) / 128, BATCH);         // (6, 16) = 96 blocks
    qconv_closed_form<<<grid, block>>>(input, theta, out);
}